// round 14
// baseline (speedup 1.0000x reference)
#include <cuda_runtime.h>

#define NVOCAB 50001   // VOCAB + 1 rows
#define EMB    32
#define UNITS  16
#define BATCH  256
#define TLEN   4096
#define GATE3  48
#define PD     8       // prefetch depth (steps)

typedef unsigned long long u64;

// Repacked, pre-scaled input projection table: [NVOCAB][64] floats.
// For lane l (l2 = l&15, c1 = l^16):
//   pos 2l   = 0.5 * (emb@kernel + bias0)[c1]       (r-col for l<16, z-col for l>=16)
//   pos 2l+1 = 0.5 * (emb@kernel + bias0)[32 + l2]  (candidate col)
__device__ float g_table2[(long)NVOCAB * 64];

__device__ __forceinline__ float tanh_ap(float x) {
    float y; asm("tanh.approx.f32 %0, %1;" : "=f"(y) : "f"(x)); return y;
}
__device__ __forceinline__ u64 fma2(u64 a, u64 b, u64 c) {
    u64 d; asm("fma.rn.f32x2 %0, %1, %2, %3;" : "=l"(d) : "l"(a), "l"(b), "l"(c));
    return d;
}
__device__ __forceinline__ u64 mul2(u64 a, u64 b) {
    u64 d; asm("mul.rn.f32x2 %0, %1, %2;" : "=l"(d) : "l"(a), "l"(b));
    return d;
}
__device__ __forceinline__ u64 add2(u64 a, u64 b) {
    u64 d; asm("add.rn.f32x2 %0, %1, %2;" : "=l"(d) : "l"(a), "l"(b));
    return d;
}
__device__ __forceinline__ u64 packf2(float lo, float hi) {
    u64 d; asm("mov.b64 %0, {%1, %2};" : "=l"(d) : "f"(lo), "f"(hi));
    return d;
}
__device__ __forceinline__ void unpackf2(u64 v, float& lo, float& hi) {
    asm("mov.b64 {%0, %1}, %2;" : "=f"(lo), "=f"(hi) : "l"(v));
}
__device__ __forceinline__ void lds_v2u64(unsigned int addr, u64& a, u64& b) {
    asm volatile("ld.shared.v2.b64 {%0, %1}, [%2];" : "=l"(a), "=l"(b) : "r"(addr));
}
__device__ __forceinline__ void sts_v2u64(unsigned int addr, u64 a, u64 b) {
    asm volatile("st.shared.v2.b64 [%0], {%1, %2};" :: "r"(addr), "l"(a), "l"(b) : "memory");
}
__device__ __forceinline__ unsigned int smem_u32(const void* p) {
    unsigned int a;
    asm("{ .reg .u64 t; cvta.to.shared.u64 t, %1; cvt.u32.u64 %0, t; }"
        : "=r"(a) : "l"(p));
    return a;
}

// ---------------------------------------------------------------------------
// Kernel A: build the repacked table.  One warp per vocab row (strided).
// ---------------------------------------------------------------------------
__global__ __launch_bounds__(128) void build_table(
    const float* __restrict__ emb,
    const float* __restrict__ kern,
    const float* __restrict__ bias)
{
    const int lane = threadIdx.x & 31;
    const int l2   = lane & 15;
    const int c1   = lane ^ 16;
    const int w    = (blockIdx.x * blockDim.x + threadIdx.x) >> 5;
    const int nw   = (gridDim.x * blockDim.x) >> 5;

    float KA[EMB], KB[EMB];
#pragma unroll
    for (int e = 0; e < EMB; e++) {
        KA[e] = kern[e * GATE3 + c1];
        KB[e] = kern[e * GATE3 + 32 + l2];
    }
    const float bA = bias[c1];
    const float bB = bias[32 + l2];

    for (int v = w; v < NVOCAB; v += nw) {
        float ev = emb[(long)v * EMB + lane];   // coalesced 128B
        float a = bA, b = bB;
#pragma unroll
        for (int e = 0; e < EMB; e++) {
            float s = __shfl_sync(0xffffffffu, ev, e);
            a = fmaf(s, KA[e], a);
            b = fmaf(s, KB[e], b);
        }
        float2 p; p.x = 0.5f * a; p.y = 0.5f * b;
        *reinterpret_cast<float2*>(&g_table2[(long)v * 64 + 2 * lane]) = p;
    }
}

// ---------------------------------------------------------------------------
// One GRU cell step for one chain. P[i] = duplicated (h[i],h[i]) pairs.
// All inputs pre-scaled by 0.5; both activations are exact sigmoids via
// MUFU tanh: sig(2y) = 0.5 + 0.5*tanh(y).
// ---------------------------------------------------------------------------
__device__ __forceinline__ float gru_cell(
    const u64* __restrict__ P, const u64* __restrict__ RP,
    float b1x, float b2, float x2, float hcur)
{
    u64 seed = packf2(b1x, b2);
    u64 cA = fma2(P[0],  RP[0],  seed);
    cA = fma2(P[1],  RP[1],  cA);
    cA = fma2(P[2],  RP[2],  cA);
    cA = fma2(P[3],  RP[3],  cA);
    u64 cB = mul2(P[4],  RP[4]);
    cB = fma2(P[5],  RP[5],  cB);
    cB = fma2(P[6],  RP[6],  cB);
    cB = fma2(P[7],  RP[7],  cB);
    u64 cC = mul2(P[8],  RP[8]);
    cC = fma2(P[9],  RP[9],  cC);
    cC = fma2(P[10], RP[10], cC);
    cC = fma2(P[11], RP[11], cC);
    u64 cD = mul2(P[12], RP[12]);
    cD = fma2(P[13], RP[13], cD);
    cD = fma2(P[14], RP[14], cD);
    cD = fma2(P[15], RP[15], cD);
    u64 s = add2(add2(cA, cB), add2(cC, cD));

    float acc1, acc2;                   // .x = gate col c1, .y = candidate col
    unpackf2(s, acc1, acc2);

    // off-critical-path prep while tanh is in flight
    float u  = 0.5f * acc2;             // 0.5*rh scaled term
    float v  = u + x2;                  // constant part of candidate arg
    float hm = hcur - 0.5f;

    float t1  = tanh_ap(acc1);                            // r (lanes<16) / z (>=16)
    float t1s = __shfl_down_sync(0xffffffffu, t1, 16);    // z's tanh -> lanes<16
    float y   = fmaf(u, t1, v);                           // 0.5*(xh + r*rh)
    float t2  = tanh_ap(y);
    float hh  = fmaf(0.5f, t2, 0.5f);                     // candidate
    float d   = fmaf(-0.5f, t2, hm);                      // hcur - hh
    float z   = fmaf(0.5f, t1s, 0.5f);
    return fmaf(z, d, hh);                                // z*h + (1-z)*hh
}

// ---------------------------------------------------------------------------
// Kernel B: GRU scan. TWO batch chains per warp (latency hiding); 2 warps per
// CTA (SMSP 0 and 1). Gate order in weights: z (0-15), r (16-31), h (32-47).
// Lane mapping: c1 = l^16 -> lanes 0-15 compute the r-column, lanes 16-31 the
// z-column with the same instructions; every lane also carries the candidate
// column 32+l2 in the .y slot of a packed f32x2 chain.
//
// State buffer: lane l2 stores ONE STS.128 = (hA,hA,hB,hB) into a ping-pong
// SMEM slot; each ld.shared.v2.b64 returns both chains' duplicated pair for
// one unit. One __syncwarp serves both chains' steps.
// ---------------------------------------------------------------------------
__global__ __launch_bounds__(64, 1) void gru_scan(
    const int*   __restrict__ ids,
    const float* __restrict__ reck,
    const float* __restrict__ bias,
    float*       __restrict__ out)
{
    __shared__ __align__(16) u64 hbuf[2][2][2 * UNITS];  // [warp][parity][unit*(A,B)]

    const int lane = threadIdx.x & 31;
    const int w    = threadIdx.x >> 5;
    const int bA   = (blockIdx.x * 2 + w) * 2;
    const int bB   = bA + 1;
    const int c1   = lane ^ 16;
    const int l2   = lane & 15;

    // packed recurrent columns: RP[i] = 0.5*(reck[i][c1], reck[i][32+l2])
    u64 RP[UNITS];
#pragma unroll
    for (int i = 0; i < UNITS; i++)
        RP[i] = packf2(0.5f * reck[i * GATE3 + c1],
                       0.5f * reck[i * GATE3 + 32 + l2]);
    const float b1 = 0.5f * bias[GATE3 + c1];
    const float b2 = 0.5f * bias[GATE3 + 32 + l2];

    const int* idA = ids + (long)bA * TLEN;
    const int* idB = ids + (long)bB * TLEN;
    const float* mytab = g_table2 + 2 * lane;

    // two-level prefetch rings: x-values PD ahead, ids 2*PD ahead
    float2 xA[PD], xB[PD];
    int    irA[PD], irB[PD];
#pragma unroll
    for (int k = 0; k < PD; k++) {
        xA[k] = *reinterpret_cast<const float2*>(mytab + ((long)idA[k] << 6));
        xB[k] = *reinterpret_cast<const float2*>(mytab + ((long)idB[k] << 6));
        irA[k] = idA[k + PD];
        irB[k] = idB[k + PD];
    }

    const unsigned int hb0 = smem_u32(&hbuf[w][0][0]);
    const unsigned int hb1 = smem_u32(&hbuf[w][1][0]);
    if (lane < 16) sts_v2u64(hb0 + l2 * 16, 0ull, 0ull);  // h = 0, parity 0
    __syncwarp();

    float hA = 0.0f, hB = 0.0f;        // lane u (<16) holds h[u] per chain

    for (int t0 = 0; t0 < TLEN; t0 += PD) {
#pragma unroll
        for (int k = 0; k < PD; k++) {
            const unsigned int rb = (k & 1) ? hb1 : hb0;
            const unsigned int wb = (k & 1) ? hb0 : hb1;

            // load both chains' duplicated h pairs (broadcast, conflict-free)
            u64 PA[UNITS], PB[UNITS];
#pragma unroll
            for (int i = 0; i < UNITS; i++)
                lds_v2u64(rb + i * 16, PA[i], PB[i]);

            const float x1a = xA[k].x, x2a = xA[k].y;
            const float x1b = xB[k].x, x2b = xB[k].y;

            // refills, PD / 2*PD steps ahead (mask-wrap; wrapped loads unused)
            xA[k] = *reinterpret_cast<const float2*>(mytab + ((long)irA[k] << 6));
            xB[k] = *reinterpret_cast<const float2*>(mytab + ((long)irB[k] << 6));
            const int tn = (t0 + k + 2 * PD) & (TLEN - 1);
            irA[k] = idA[tn];
            irB[k] = idB[tn];

            const float hnA = gru_cell(PA, RP, b1 + x1a, b2, x2a, hA);
            const float hnB = gru_cell(PB, RP, b1 + x1b, b2, x2b, hB);
            hA = hnA; hB = hnB;

            if (lane < 16)
                sts_v2u64(wb + l2 * 16, packf2(hnA, hnA), packf2(hnB, hnB));
            __syncwarp();
        }
    }

    if (lane < 16) {
        out[(long)bA * UNITS + lane] = hA;
        out[(long)bB * UNITS + lane] = hB;
    }
}

// ---------------------------------------------------------------------------
extern "C" void kernel_launch(void* const* d_in, const int* in_sizes, int n_in,
                              void* d_out, int out_size)
{
    const int*   ids  = (const int*)  d_in[0];   // [256, 4096] int32
    const float* emb  = (const float*)d_in[1];   // [50001, 32]
    const float* kern = (const float*)d_in[2];   // [32, 48]
    const float* reck = (const float*)d_in[3];   // [16, 48]
    const float* bias = (const float*)d_in[4];   // [2, 48]
    float*       out  = (float*)d_out;           // [256, 16]

    (void)in_sizes; (void)n_in; (void)out_size;

    build_table<<<256, 128>>>(emb, kern, bias);
    gru_scan<<<BATCH / 4, 64>>>(ids, reck, bias, out);
}

// round 15
// speedup vs baseline: 1.3228x; 1.3228x over previous
#include <cuda_runtime.h>

#define NVOCAB 50001   // VOCAB + 1 rows
#define EMB    32
#define UNITS  16
#define BATCH  256
#define TLEN   4096
#define GATE3  48
#define PD     8       // prefetch depth (steps)

typedef unsigned long long u64;

// Repacked, pre-scaled input projection table: [NVOCAB][64] floats.
// For lane l (l2 = l&15, c1 = l^16):
//   pos 2l   = 0.5 * (emb@kernel + bias0 + bias1)[c1]   (gate col: r for l<16, z for l>=16,
//                                                        recurrent bias FOLDED IN)
//   pos 2l+1 = 0.5 * (emb@kernel + bias0)[32 + l2]      (candidate col, b2 stays separate:
//                                                        it lives inside the r*(...) term)
__device__ float g_table2[(long)NVOCAB * 64];

__device__ __forceinline__ float tanh_ap(float x) {
    float y; asm("tanh.approx.f32 %0, %1;" : "=f"(y) : "f"(x)); return y;
}
__device__ __forceinline__ u64 fma2(u64 a, u64 b, u64 c) {
    u64 d; asm("fma.rn.f32x2 %0, %1, %2, %3;" : "=l"(d) : "l"(a), "l"(b), "l"(c));
    return d;
}
__device__ __forceinline__ u64 mul2(u64 a, u64 b) {
    u64 d; asm("mul.rn.f32x2 %0, %1, %2;" : "=l"(d) : "l"(a), "l"(b));
    return d;
}
__device__ __forceinline__ u64 add2(u64 a, u64 b) {
    u64 d; asm("add.rn.f32x2 %0, %1, %2;" : "=l"(d) : "l"(a), "l"(b));
    return d;
}
__device__ __forceinline__ u64 packf2(float lo, float hi) {
    u64 d; asm("mov.b64 %0, {%1, %2};" : "=l"(d) : "f"(lo), "f"(hi));
    return d;
}
__device__ __forceinline__ void unpackf2(u64 v, float& lo, float& hi) {
    asm("mov.b64 {%0, %1}, %2;" : "=f"(lo), "=f"(hi) : "l"(v));
}
__device__ __forceinline__ void lds_v2u64(unsigned int addr, u64& a, u64& b) {
    asm volatile("ld.shared.v2.b64 {%0, %1}, [%2];" : "=l"(a), "=l"(b) : "r"(addr));
}
__device__ __forceinline__ void sts_u64(unsigned int addr, u64 v) {
    asm volatile("st.shared.b64 [%0], %1;" :: "r"(addr), "l"(v) : "memory");
}
__device__ __forceinline__ unsigned int smem_u32(const void* p) {
    unsigned int a;
    asm("{ .reg .u64 t; cvta.to.shared.u64 t, %1; cvt.u32.u64 %0, t; }"
        : "=r"(a) : "l"(p));
    return a;
}

// ---------------------------------------------------------------------------
// Kernel A: build the repacked table.  One warp per vocab row (strided).
// Gate column gets BOTH biases folded in (input + recurrent); candidate
// column gets only the input bias.
// ---------------------------------------------------------------------------
__global__ __launch_bounds__(128) void build_table(
    const float* __restrict__ emb,
    const float* __restrict__ kern,
    const float* __restrict__ bias)
{
    const int lane = threadIdx.x & 31;
    const int l2   = lane & 15;
    const int c1   = lane ^ 16;
    const int w    = (blockIdx.x * blockDim.x + threadIdx.x) >> 5;
    const int nw   = (gridDim.x * blockDim.x) >> 5;

    float KA[EMB], KB[EMB];
#pragma unroll
    for (int e = 0; e < EMB; e++) {
        KA[e] = kern[e * GATE3 + c1];
        KB[e] = kern[e * GATE3 + 32 + l2];
    }
    const float bA = bias[c1] + bias[GATE3 + c1];   // b0 + b1, gate col
    const float bB = bias[32 + l2];                 // b0 only, candidate col

    for (int v = w; v < NVOCAB; v += nw) {
        float ev = emb[(long)v * EMB + lane];   // coalesced 128B
        float a = bA, b = bB;
#pragma unroll
        for (int e = 0; e < EMB; e++) {
            float s = __shfl_sync(0xffffffffu, ev, e);
            a = fmaf(s, KA[e], a);
            b = fmaf(s, KB[e], b);
        }
        float2 p; p.x = 0.5f * a; p.y = 0.5f * b;
        *reinterpret_cast<float2*>(&g_table2[(long)v * 64 + 2 * lane]) = p;
    }
}

// ---------------------------------------------------------------------------
// Kernel B: GRU scan. ONE batch chain per warp; 2 warps per CTA (SMSP 0/1).
// Gate order in weights: z (0-15), r (16-31), h (32-47).
// Lane mapping: c1 = l^16 -> lanes 0-15 compute the r-column, lanes 16-31 the
// z-column with the SAME instructions; every lane also carries the candidate
// column 32+l2 in the .y slot of a packed f32x2 chain.
//
// State hand-off WITHOUT __syncwarp: the step body has no branches, so the
// warp stays converged; the STS (end of step t) and the LDS (start of step
// t+1) are warp-wide instructions issued in program order through the
// in-order LSU, so the load observes the store. Both are asm volatile, so
// the compiler cannot reorder them either. Single buffer (no ping-pong):
// within a step the LDS precedes the STS in program order, so the read gets
// the old state before the write lands.
// Everything pre-scaled by 0.5; both activations are exact sigmoids via
// MUFU tanh: sig(2y) = 0.5 + 0.5*tanh(y).
// ---------------------------------------------------------------------------
__global__ __launch_bounds__(64, 1) void gru_scan(
    const int*   __restrict__ ids,
    const float* __restrict__ reck,
    const float* __restrict__ bias,
    float*       __restrict__ out)
{
    __shared__ __align__(16) u64 hbuf[2][UNITS];   // [warp][unit] duplicated (h,h)

    const int lane = threadIdx.x & 31;
    const int w    = threadIdx.x >> 5;
    const int b    = blockIdx.x * 2 + w;
    const int c1   = lane ^ 16;
    const int l2   = lane & 15;

    // packed recurrent columns: RP[i] = 0.5*(reck[i][c1], reck[i][32+l2])
    u64 RP[UNITS];
#pragma unroll
    for (int i = 0; i < UNITS; i++)
        RP[i] = packf2(0.5f * reck[i * GATE3 + c1],
                       0.5f * reck[i * GATE3 + 32 + l2]);
    const float b2 = 0.5f * bias[GATE3 + 32 + l2];   // recurrent bias, cand col

    const int* idp = ids + (long)b * TLEN;
    const float* mytab = g_table2 + 2 * lane;

    // two-level prefetch rings: x-values PD ahead, ids 2*PD ahead
    float2 xb[PD];
    int    ir[PD];
#pragma unroll
    for (int k = 0; k < PD; k++) {
        xb[k] = *reinterpret_cast<const float2*>(mytab + ((long)idp[k] << 6));
        ir[k] = idp[k + PD];
    }

    const unsigned int hb = smem_u32(&hbuf[w][0]);
    const unsigned int ws = hb + l2 * 8;             // this lane's store slot
    if (lane < 16) sts_u64(ws, 0ull);                // h = 0
    __syncwarp();                                    // once, before the loop

    float hcur = 0.0f;                               // lane u (<16) holds h[u]

    for (int t0 = 0; t0 < TLEN; t0 += PD) {
#pragma unroll
        for (int k = 0; k < PD; k++) {
            // load duplicated h pairs (broadcast, conflict-free)
            u64 P[UNITS];
#pragma unroll
            for (int i = 0; i < UNITS; i += 2)
                lds_v2u64(hb + i * 8, P[i], P[i + 1]);

            const float x1 = xb[k].x;    // 0.5*(xproj + b0 + b1)[c1]
            const float x2 = xb[k].y;    // 0.5*(xproj + b0)[32+l2]

            // packed dual matvec: .x gate col c1, .y candidate col 32+l2
            u64 seed = packf2(x1, b2);
            u64 cA = fma2(P[0],  RP[0],  seed);
            cA = fma2(P[1],  RP[1],  cA);
            cA = fma2(P[2],  RP[2],  cA);
            cA = fma2(P[3],  RP[3],  cA);
            u64 cB = mul2(P[4],  RP[4]);
            cB = fma2(P[5],  RP[5],  cB);
            cB = fma2(P[6],  RP[6],  cB);
            cB = fma2(P[7],  RP[7],  cB);
            u64 cC = mul2(P[8],  RP[8]);
            cC = fma2(P[9],  RP[9],  cC);
            cC = fma2(P[10], RP[10], cC);
            cC = fma2(P[11], RP[11], cC);
            u64 cD = mul2(P[12], RP[12]);
            cD = fma2(P[13], RP[13], cD);
            cD = fma2(P[14], RP[14], cD);
            cD = fma2(P[15], RP[15], cD);
            u64 s = add2(add2(cA, cB), add2(cC, cD));

            float acc1, acc2;            // unpack = register naming only
            unpackf2(s, acc1, acc2);

            // off-critical-path prep while tanh is in flight
            float u  = 0.5f * acc2;      // 0.5*rh term
            float v  = u + x2;           // constant part of candidate arg
            float hm = hcur - 0.5f;

            float t1  = tanh_ap(acc1);                          // r (<16) / z (>=16)
            float t1s = __shfl_down_sync(0xffffffffu, t1, 16);  // z's tanh
            float y   = fmaf(u, t1, v);                         // 0.5*(xh + r*rh)
            float t2  = tanh_ap(y);
            float hh  = fmaf(0.5f, t2, 0.5f);                   // candidate
            float d   = fmaf(-0.5f, t2, hm);                    // hcur - hh
            float z   = fmaf(0.5f, t1s, 0.5f);
            float hn  = fmaf(z, d, hh);                         // z*h + (1-z)*hh
            hcur = hn;

            // publish new state (duplicated pair); no sync needed — see header
            if (lane < 16) sts_u64(ws, packf2(hn, hn));

            // ring refills (independent, off the critical path)
            xb[k] = *reinterpret_cast<const float2*>(mytab + ((long)ir[k] << 6));
            ir[k] = idp[(t0 + k + 2 * PD) & (TLEN - 1)];
        }
    }

    if (lane < 16) out[(long)b * UNITS + lane] = hcur;
}

// ---------------------------------------------------------------------------
extern "C" void kernel_launch(void* const* d_in, const int* in_sizes, int n_in,
                              void* d_out, int out_size)
{
    const int*   ids  = (const int*)  d_in[0];   // [256, 4096] int32
    const float* emb  = (const float*)d_in[1];   // [50001, 32]
    const float* kern = (const float*)d_in[2];   // [32, 48]
    const float* reck = (const float*)d_in[3];   // [16, 48]
    const float* bias = (const float*)d_in[4];   // [2, 48]
    float*       out  = (float*)d_out;           // [256, 16]

    (void)in_sizes; (void)n_in; (void)out_size;

    build_table<<<256, 128>>>(emb, kern, bias);
    gru_scan<<<BATCH / 2, 64>>>(ids, reck, bias, out);
}